// round 1
// baseline (speedup 1.0000x reference)
#include <cuda_runtime.h>

// Problem constants
#define Bsz   2
#define Sseq  2048
#define Dm    1024
#define Hh    16
#define DKh   64
#define Mrows (Bsz * Sseq)   // 4096

// Scratch (allocation-free rule: __device__ globals)
__device__ float g_Qp[Mrows * Dm];
__device__ float g_Kp[Mrows * Dm];
__device__ float g_Vp[Mrows * Dm];
__device__ float g_Ctx[Mrows * Dm];

// ---------------------------------------------------------------------------
// GEMM: C[M,N] = A[M,K] @ W[N,K]^T + bias[N]   (torch Linear convention)
// 128x128 tile, BK=16, 256 threads, 8x8 per-thread microtile.
// ---------------------------------------------------------------------------
#define BM 128
#define BN 128
#define BK 16

__global__ __launch_bounds__(256)
void gemm_nt_bias(const float* __restrict__ A, const float* __restrict__ W,
                  const float* __restrict__ bias, float* __restrict__ C,
                  int M, int N, int K)
{
    __shared__ float As[BK][BM + 4];
    __shared__ float Bs[BK][BN + 4];

    const int tid = threadIdx.x;
    const int tx  = tid & 15;       // 0..15
    const int ty  = tid >> 4;       // 0..15
    const int bM  = blockIdx.y * BM;
    const int bN  = blockIdx.x * BN;

    // load mapping: 4 threads per row-segment of 16 floats
    const int lr = tid >> 2;          // 0..63
    const int lc = (tid & 3) << 2;    // 0,4,8,12

    const float* Ap = A + (size_t)(bM + lr) * K + lc;
    const float* Wp = W + (size_t)(bN + lr) * K + lc;

    float acc[8][8];
    #pragma unroll
    for (int i = 0; i < 8; i++)
        #pragma unroll
        for (int j = 0; j < 8; j++) acc[i][j] = 0.f;

    for (int k0 = 0; k0 < K; k0 += BK) {
        #pragma unroll
        for (int i = 0; i < 2; i++) {
            const int row = lr + i * 64;
            float4 a = *(const float4*)(Ap + (size_t)(i * 64) * K + k0);
            As[lc + 0][row] = a.x; As[lc + 1][row] = a.y;
            As[lc + 2][row] = a.z; As[lc + 3][row] = a.w;
            float4 b = *(const float4*)(Wp + (size_t)(i * 64) * K + k0);
            Bs[lc + 0][row] = b.x; Bs[lc + 1][row] = b.y;
            Bs[lc + 2][row] = b.z; Bs[lc + 3][row] = b.w;
        }
        __syncthreads();

        #pragma unroll
        for (int kk = 0; kk < BK; kk++) {
            float a[8], b[8];
            *(float4*)&a[0] = *(const float4*)&As[kk][ty * 8 + 0];
            *(float4*)&a[4] = *(const float4*)&As[kk][ty * 8 + 4];
            *(float4*)&b[0] = *(const float4*)&Bs[kk][tx * 8 + 0];
            *(float4*)&b[4] = *(const float4*)&Bs[kk][tx * 8 + 4];
            #pragma unroll
            for (int i = 0; i < 8; i++)
                #pragma unroll
                for (int j = 0; j < 8; j++)
                    acc[i][j] += a[i] * b[j];
        }
        __syncthreads();
    }

    #pragma unroll
    for (int i = 0; i < 8; i++) {
        const size_t r = (size_t)(bM + ty * 8 + i) * N + bN + tx * 8;
        #pragma unroll
        for (int j = 0; j < 8; j += 4) {
            float4 o;
            o.x = acc[i][j + 0] + bias[bN + tx * 8 + j + 0];
            o.y = acc[i][j + 1] + bias[bN + tx * 8 + j + 1];
            o.z = acc[i][j + 2] + bias[bN + tx * 8 + j + 2];
            o.w = acc[i][j + 3] + bias[bN + tx * 8 + j + 3];
            *(float4*)&C[r + j] = o;
        }
    }
}

// ---------------------------------------------------------------------------
// Flash attention: one thread per query row. 128 query rows per block.
// K/V tiles of 64 keys in smem (broadcast reads). Online softmax.
// Reads head slices directly from [B,S,D] projection buffers (col offset h*64).
// ---------------------------------------------------------------------------
#define TQ 128
#define TK 64

__global__ __launch_bounds__(128)
void flash_attn()
{
    __shared__ float Ks[TK][DKh];
    __shared__ float Vs[TK][DKh];

    const int tid = threadIdx.x;
    const int b   = blockIdx.z;
    const int h   = blockIdx.y;
    const int row = blockIdx.x * TQ + tid;

    const size_t base = (size_t)b * Sseq * Dm + (size_t)h * DKh;
    const float* Qg = g_Qp + base;
    const float* Kg = g_Kp + base;
    const float* Vg = g_Vp + base;
    float*       Og = g_Ctx + base;

    float q[DKh], o[DKh];
    #pragma unroll
    for (int d = 0; d < DKh; d += 4) {
        float4 t = *(const float4*)&Qg[(size_t)row * Dm + d];
        q[d + 0] = t.x * 0.125f;   // 1/sqrt(64)
        q[d + 1] = t.y * 0.125f;
        q[d + 2] = t.z * 0.125f;
        q[d + 3] = t.w * 0.125f;
        o[d + 0] = 0.f; o[d + 1] = 0.f; o[d + 2] = 0.f; o[d + 3] = 0.f;
    }
    float m = -1e30f, l = 0.f;

    for (int kv0 = 0; kv0 < Sseq; kv0 += TK) {
        __syncthreads();
        // cooperative tile load: TK rows x 16 float4
        for (int i = tid; i < TK * (DKh / 4); i += TQ) {
            const int r = i >> 4;
            const int c = (i & 15) << 2;
            *(float4*)&Ks[r][c] = *(const float4*)&Kg[(size_t)(kv0 + r) * Dm + c];
            *(float4*)&Vs[r][c] = *(const float4*)&Vg[(size_t)(kv0 + r) * Dm + c];
        }
        __syncthreads();

        for (int kk = 0; kk < TK; kk++) {
            float s0 = 0.f, s1 = 0.f, s2 = 0.f, s3 = 0.f;
            #pragma unroll
            for (int d = 0; d < DKh; d += 4) {
                s0 += q[d + 0] * Ks[kk][d + 0];
                s1 += q[d + 1] * Ks[kk][d + 1];
                s2 += q[d + 2] * Ks[kk][d + 2];
                s3 += q[d + 3] * Ks[kk][d + 3];
            }
            const float s  = (s0 + s1) + (s2 + s3);
            const float mn = fmaxf(m, s);
            const float p  = __expf(s - mn);
            if (mn > m) {
                const float sc = __expf(m - mn);
                l *= sc;
                #pragma unroll
                for (int d = 0; d < DKh; d++) o[d] *= sc;
                m = mn;
            }
            l += p;
            #pragma unroll
            for (int d = 0; d < DKh; d++) o[d] += p * Vs[kk][d];
        }
    }

    const float inv = 1.f / l;
    #pragma unroll
    for (int d = 0; d < DKh; d += 4) {
        float4 t;
        t.x = o[d + 0] * inv; t.y = o[d + 1] * inv;
        t.z = o[d + 2] * inv; t.w = o[d + 3] * inv;
        *(float4*)&Og[(size_t)row * Dm + d] = t;
    }
}

// ---------------------------------------------------------------------------
// Launch
// ---------------------------------------------------------------------------
extern "C" void kernel_launch(void* const* d_in, const int* in_sizes, int n_in,
                              void* d_out, int out_size)
{
    const float* q  = (const float*)d_in[0];
    const float* k  = (const float*)d_in[1];
    const float* v  = (const float*)d_in[2];
    const float* wq = (const float*)d_in[3];
    const float* bq = (const float*)d_in[4];
    const float* wk = (const float*)d_in[5];
    const float* bk = (const float*)d_in[6];
    const float* wv = (const float*)d_in[7];
    const float* bv = (const float*)d_in[8];
    const float* wo = (const float*)d_in[9];
    const float* bo = (const float*)d_in[10];
    float* out = (float*)d_out;

    float *Qp, *Kp, *Vp, *Ctx;
    cudaGetSymbolAddress((void**)&Qp,  g_Qp);
    cudaGetSymbolAddress((void**)&Kp,  g_Kp);
    cudaGetSymbolAddress((void**)&Vp,  g_Vp);
    cudaGetSymbolAddress((void**)&Ctx, g_Ctx);

    const dim3 gg(Dm / BN, Mrows / BM);   // (8, 32)
    gemm_nt_bias<<<gg, 256>>>(q, wq, bq, Qp, Mrows, Dm, Dm);
    gemm_nt_bias<<<gg, 256>>>(k, wk, bk, Kp, Mrows, Dm, Dm);
    gemm_nt_bias<<<gg, 256>>>(v, wv, bv, Vp, Mrows, Dm, Dm);

    const dim3 ga(Sseq / TQ, Hh, Bsz);    // (16, 16, 2)
    flash_attn<<<ga, TQ>>>();

    gemm_nt_bias<<<gg, 256>>>(Ctx, wo, bo, out, Mrows, Dm, Dm);
}

// round 2
// speedup vs baseline: 1.3216x; 1.3216x over previous
#include <cuda_runtime.h>
#include <cuda_bf16.h>
#include <cstdint>

// Problem constants
#define Bsz   2
#define Sseq  2048
#define Dm    1024
#define Hh    16
#define DKh   64
#define Mrows (Bsz * Sseq)   // 4096

// Scratch (allocation-free rule: __device__ globals)
__device__ float g_Qp[Mrows * Dm];
__device__ float g_Kp[Mrows * Dm];
__device__ float g_Vp[Mrows * Dm];
__device__ float g_Ctx[Mrows * Dm];

// ===========================================================================
// Tensor-core GEMM: C[M,N] = A[M,K] @ W[N,K]^T + bias[N]
// bf16 3-way split (hi/lo) via mma.sync.m16n8k16 -> fp32-accurate to ~3e-5.
// Block 128x128, k-chunk 32, 256 threads = 8 warps (4m x 2n), warp tile 32x64.
// ===========================================================================
#define GBM 128
#define GBN 128
#define GBK 32
#define GLD (GBK + 8)   // padded smem row stride (conflict-free fragment LDS)

__device__ __forceinline__ void mma16816(float* c, const uint32_t* a, const uint32_t* b)
{
    asm volatile(
        "mma.sync.aligned.m16n8k16.row.col.f32.bf16.bf16.f32 "
        "{%0,%1,%2,%3}, {%4,%5,%6,%7}, {%8,%9}, {%0,%1,%2,%3};\n"
        : "+f"(c[0]), "+f"(c[1]), "+f"(c[2]), "+f"(c[3])
        : "r"(a[0]), "r"(a[1]), "r"(a[2]), "r"(a[3]), "r"(b[0]), "r"(b[1]));
}

__device__ __forceinline__ void split_store(__nv_bfloat16* hi, __nv_bfloat16* lo,
                                            float x, float y)
{
    __nv_bfloat16 hx = __float2bfloat16(x);
    __nv_bfloat16 hy = __float2bfloat16(y);
    __nv_bfloat16 lx = __float2bfloat16(x - __bfloat162float(hx));
    __nv_bfloat16 ly = __float2bfloat16(y - __bfloat162float(hy));
    *(__nv_bfloat162*)hi = __nv_bfloat162(hx, hy);
    *(__nv_bfloat162*)lo = __nv_bfloat162(lx, ly);
}

__global__ __launch_bounds__(256)
void gemm_nt_bias_tc(const float* __restrict__ A, const float* __restrict__ W,
                     const float* __restrict__ bias, float* __restrict__ C,
                     int M, int N, int K)
{
    __shared__ __nv_bfloat16 Ah[GBM][GLD], Al[GBM][GLD];
    __shared__ __nv_bfloat16 Wh[GBN][GLD], Wl[GBN][GLD];

    const int tid  = threadIdx.x;
    const int lane = tid & 31;
    const int warp = tid >> 5;
    const int wm   = warp & 3;            // 0..3 (m)
    const int wn   = warp >> 2;           // 0..1 (n)
    const int g    = lane >> 2;           // 0..7
    const int tg   = lane & 3;            // 0..3
    const int bM   = blockIdx.y * GBM;
    const int bN   = blockIdx.x * GBN;

    // gmem->smem mapping: thread loads one row-half of 16 floats
    const int lr = tid >> 1;              // 0..127
    const int lc = (tid & 1) * 16;        // 0 or 16

    const float* Ap = A + (size_t)(bM + lr) * K + lc;
    const float* Wp = W + (size_t)(bN + lr) * K + lc;

    float acc[2][8][4];
    #pragma unroll
    for (int i = 0; i < 2; i++)
        #pragma unroll
        for (int j = 0; j < 8; j++)
            #pragma unroll
            for (int t = 0; t < 4; t++) acc[i][j][t] = 0.f;

    for (int k0 = 0; k0 < K; k0 += GBK) {
        float4 av[4], wv[4];
        #pragma unroll
        for (int j = 0; j < 4; j++) {
            av[j] = *(const float4*)(Ap + k0 + j * 4);
            wv[j] = *(const float4*)(Wp + k0 + j * 4);
        }
        __syncthreads();   // previous chunk's compute done
        #pragma unroll
        for (int j = 0; j < 4; j++) {
            const int c = lc + j * 4;
            split_store(&Ah[lr][c + 0], &Al[lr][c + 0], av[j].x, av[j].y);
            split_store(&Ah[lr][c + 2], &Al[lr][c + 2], av[j].z, av[j].w);
            split_store(&Wh[lr][c + 0], &Wl[lr][c + 0], wv[j].x, wv[j].y);
            split_store(&Wh[lr][c + 2], &Wl[lr][c + 2], wv[j].z, wv[j].w);
        }
        __syncthreads();

        #pragma unroll
        for (int ks = 0; ks < GBK; ks += 16) {
            uint32_t ah[2][4], al[2][4], bh[8][2], bl[8][2];
            #pragma unroll
            for (int mt = 0; mt < 2; mt++) {
                const int r0 = wm * 32 + mt * 16;
                ah[mt][0] = *(const uint32_t*)&Ah[r0 + g    ][ks + 2 * tg    ];
                ah[mt][1] = *(const uint32_t*)&Ah[r0 + 8 + g][ks + 2 * tg    ];
                ah[mt][2] = *(const uint32_t*)&Ah[r0 + g    ][ks + 2 * tg + 8];
                ah[mt][3] = *(const uint32_t*)&Ah[r0 + 8 + g][ks + 2 * tg + 8];
                al[mt][0] = *(const uint32_t*)&Al[r0 + g    ][ks + 2 * tg    ];
                al[mt][1] = *(const uint32_t*)&Al[r0 + 8 + g][ks + 2 * tg    ];
                al[mt][2] = *(const uint32_t*)&Al[r0 + g    ][ks + 2 * tg + 8];
                al[mt][3] = *(const uint32_t*)&Al[r0 + 8 + g][ks + 2 * tg + 8];
            }
            #pragma unroll
            for (int nt = 0; nt < 8; nt++) {
                const int c0 = wn * 64 + nt * 8;
                bh[nt][0] = *(const uint32_t*)&Wh[c0 + g][ks + 2 * tg    ];
                bh[nt][1] = *(const uint32_t*)&Wh[c0 + g][ks + 2 * tg + 8];
                bl[nt][0] = *(const uint32_t*)&Wl[c0 + g][ks + 2 * tg    ];
                bl[nt][1] = *(const uint32_t*)&Wl[c0 + g][ks + 2 * tg + 8];
            }
            #pragma unroll
            for (int mt = 0; mt < 2; mt++)
                #pragma unroll
                for (int nt = 0; nt < 8; nt++) {
                    mma16816(acc[mt][nt], ah[mt], bh[nt]);
                    mma16816(acc[mt][nt], ah[mt], bl[nt]);
                    mma16816(acc[mt][nt], al[mt], bh[nt]);
                }
        }
    }

    // epilogue: bias + store
    #pragma unroll
    for (int mt = 0; mt < 2; mt++) {
        #pragma unroll
        for (int nt = 0; nt < 8; nt++) {
            const int col = bN + wn * 64 + nt * 8 + 2 * tg;
            const float b0 = bias[col], b1 = bias[col + 1];
            const int r0 = bM + wm * 32 + mt * 16 + g;
            float2 v0 = make_float2(acc[mt][nt][0] + b0, acc[mt][nt][1] + b1);
            float2 v1 = make_float2(acc[mt][nt][2] + b0, acc[mt][nt][3] + b1);
            *(float2*)&C[(size_t)r0 * N + col]       = v0;
            *(float2*)&C[(size_t)(r0 + 8) * N + col] = v1;
        }
    }
}

// ===========================================================================
// Flash attention, packed f32x2 (FFMA2) + 8-key chunked online softmax.
// One thread per query row, 128 query rows per block, 64-key smem tiles.
// ===========================================================================
#define TQ 128
#define TK 64
#define CH 8

typedef unsigned long long u64;

__device__ __forceinline__ u64 pk2(float lo, float hi)
{
    u64 r; asm("mov.b64 %0, {%1, %2};" : "=l"(r) : "f"(lo), "f"(hi)); return r;
}
__device__ __forceinline__ void upk2(float& lo, float& hi, u64 v)
{
    asm("mov.b64 {%0, %1}, %2;" : "=f"(lo), "=f"(hi) : "l"(v));
}
__device__ __forceinline__ void fma2(u64& d, u64 a, u64 b)
{
    asm("fma.rn.f32x2 %0, %1, %2, %0;" : "+l"(d) : "l"(a), "l"(b));
}
__device__ __forceinline__ u64 mul2(u64 a, u64 b)
{
    u64 r; asm("mul.rn.f32x2 %0, %1, %2;" : "=l"(r) : "l"(a), "l"(b)); return r;
}

__global__ __launch_bounds__(128)
void flash_attn()
{
    __shared__ float Ks[TK][DKh];
    __shared__ float Vs[TK][DKh];

    const int tid = threadIdx.x;
    const int b   = blockIdx.z;
    const int h   = blockIdx.y;
    const int row = blockIdx.x * TQ + tid;

    const size_t base = (size_t)b * Sseq * Dm + (size_t)h * DKh;
    const float* Qg = g_Qp + base;
    const float* Kg = g_Kp + base;
    const float* Vg = g_Vp + base;
    float*       Og = g_Ctx + base;

    u64 q2[DKh / 2], o2[DKh / 2];
    const u64 zz = pk2(0.f, 0.f);
    #pragma unroll
    for (int d = 0; d < DKh; d += 4) {
        float4 t = *(const float4*)&Qg[(size_t)row * Dm + d];
        q2[d / 2]     = pk2(t.x * 0.125f, t.y * 0.125f);   // 1/sqrt(64)
        q2[d / 2 + 1] = pk2(t.z * 0.125f, t.w * 0.125f);
        o2[d / 2]     = zz;
        o2[d / 2 + 1] = zz;
    }
    float m = -1e30f, l = 0.f;

    for (int kv0 = 0; kv0 < Sseq; kv0 += TK) {
        __syncthreads();
        for (int i = tid; i < TK * (DKh / 4); i += TQ) {
            const int r = i >> 4;
            const int c = (i & 15) << 2;
            *(float4*)&Ks[r][c] = *(const float4*)&Kg[(size_t)(kv0 + r) * Dm + c];
            *(float4*)&Vs[r][c] = *(const float4*)&Vg[(size_t)(kv0 + r) * Dm + c];
        }
        __syncthreads();

        for (int kk0 = 0; kk0 < TK; kk0 += CH) {
            // ---- 8 independent packed dot products ----
            u64 s2[CH];
            #pragma unroll
            for (int u = 0; u < CH; u++) s2[u] = zz;
            #pragma unroll
            for (int d4 = 0; d4 < DKh / 4; d4++) {
                #pragma unroll
                for (int u = 0; u < CH; u++) {
                    const ulonglong2 kv = *(const ulonglong2*)&Ks[kk0 + u][d4 * 4];
                    fma2(s2[u], q2[d4 * 2],     kv.x);
                    fma2(s2[u], q2[d4 * 2 + 1], kv.y);
                }
            }
            float s[CH];
            #pragma unroll
            for (int u = 0; u < CH; u++) {
                float a, c; upk2(a, c, s2[u]); s[u] = a + c;
            }
            // ---- chunk max + single rescale ----
            float mc = s[0];
            #pragma unroll
            for (int u = 1; u < CH; u++) mc = fmaxf(mc, s[u]);
            const float mn = fmaxf(m, mc);
            const float sc = __expf(m - mn);
            m = mn;
            l *= sc;
            const u64 sc2 = pk2(sc, sc);
            #pragma unroll
            for (int d2 = 0; d2 < DKh / 2; d2++) o2[d2] = mul2(o2[d2], sc2);
            // ---- probabilities ----
            u64 p2[CH];
            #pragma unroll
            for (int u = 0; u < CH; u++) {
                const float p = __expf(s[u] - mn);
                l += p;
                p2[u] = pk2(p, p);
            }
            // ---- accumulate p * V (d-parallel chains) ----
            #pragma unroll
            for (int u = 0; u < CH; u++) {
                #pragma unroll
                for (int d4 = 0; d4 < DKh / 4; d4++) {
                    const ulonglong2 vv = *(const ulonglong2*)&Vs[kk0 + u][d4 * 4];
                    fma2(o2[d4 * 2],     p2[u], vv.x);
                    fma2(o2[d4 * 2 + 1], p2[u], vv.y);
                }
            }
        }
    }

    const float inv = 1.f / l;
    const u64 inv2 = pk2(inv, inv);
    #pragma unroll
    for (int d = 0; d < DKh; d += 4) {
        const u64 r0 = mul2(o2[d / 2], inv2);
        const u64 r1 = mul2(o2[d / 2 + 1], inv2);
        float4 t;
        upk2(t.x, t.y, r0);
        upk2(t.z, t.w, r1);
        *(float4*)&Og[(size_t)row * Dm + d] = t;
    }
}

// ---------------------------------------------------------------------------
// Launch
// ---------------------------------------------------------------------------
extern "C" void kernel_launch(void* const* d_in, const int* in_sizes, int n_in,
                              void* d_out, int out_size)
{
    const float* q  = (const float*)d_in[0];
    const float* k  = (const float*)d_in[1];
    const float* v  = (const float*)d_in[2];
    const float* wq = (const float*)d_in[3];
    const float* bq = (const float*)d_in[4];
    const float* wk = (const float*)d_in[5];
    const float* bk = (const float*)d_in[6];
    const float* wv = (const float*)d_in[7];
    const float* bv = (const float*)d_in[8];
    const float* wo = (const float*)d_in[9];
    const float* bo = (const float*)d_in[10];
    float* out = (float*)d_out;

    float *Qp, *Kp, *Vp, *Ctx;
    cudaGetSymbolAddress((void**)&Qp,  g_Qp);
    cudaGetSymbolAddress((void**)&Kp,  g_Kp);
    cudaGetSymbolAddress((void**)&Vp,  g_Vp);
    cudaGetSymbolAddress((void**)&Ctx, g_Ctx);

    const dim3 gg(Dm / GBN, Mrows / GBM);   // (8, 32)
    gemm_nt_bias_tc<<<gg, 256>>>(q, wq, bq, Qp, Mrows, Dm, Dm);
    gemm_nt_bias_tc<<<gg, 256>>>(k, wk, bk, Kp, Mrows, Dm, Dm);
    gemm_nt_bias_tc<<<gg, 256>>>(v, wv, bv, Vp, Mrows, Dm, Dm);

    const dim3 ga(Sseq / TQ, Hh, Bsz);      // (16, 16, 2)
    flash_attn<<<ga, TQ>>>();

    gemm_nt_bias_tc<<<gg, 256>>>(Ctx, wo, bo, out, Mrows, Dm, Dm);
}

// round 3
// speedup vs baseline: 2.6731x; 2.0226x over previous
#include <cuda_runtime.h>
#include <cuda_bf16.h>
#include <cstdint>

// Problem constants
#define Bsz   2
#define Sseq  2048
#define Dm    1024
#define Hh    16
#define DKh   64
#define Mrows (Bsz * Sseq)   // 4096

// Scratch (allocation-free rule: __device__ globals)
__device__ __nv_bfloat16 g_Qh[Mrows * Dm], g_Ql[Mrows * Dm];
__device__ __nv_bfloat16 g_Kh[Mrows * Dm], g_Kl[Mrows * Dm];
__device__ __nv_bfloat16 g_Vth[Mrows * Dm], g_Vtl[Mrows * Dm];  // [b][h][d][s]
__device__ float g_Ctx[Mrows * Dm];

// ===========================================================================
// mma.m16n8k16 bf16 wrapper
// ===========================================================================
__device__ __forceinline__ void mma16816(float* c, const uint32_t* a, uint32_t b0, uint32_t b1)
{
    asm volatile(
        "mma.sync.aligned.m16n8k16.row.col.f32.bf16.bf16.f32 "
        "{%0,%1,%2,%3}, {%4,%5,%6,%7}, {%8,%9}, {%0,%1,%2,%3};\n"
        : "+f"(c[0]), "+f"(c[1]), "+f"(c[2]), "+f"(c[3])
        : "r"(a[0]), "r"(a[1]), "r"(a[2]), "r"(a[3]), "r"(b0), "r"(b1));
}

__device__ __forceinline__ uint32_t pack_hi2(float x, float y)
{
    __nv_bfloat162 t(__float2bfloat16(x), __float2bfloat16(y));
    return *(uint32_t*)&t;
}
// residual after bf16 truncation, packed
__device__ __forceinline__ void split2(float x, float y, uint32_t& hi, uint32_t& lo)
{
    __nv_bfloat16 hx = __float2bfloat16(x), hy = __float2bfloat16(y);
    __nv_bfloat16 lx = __float2bfloat16(x - __bfloat162float(hx));
    __nv_bfloat16 ly = __float2bfloat16(y - __bfloat162float(hy));
    __nv_bfloat162 h(hx, hy), l(lx, ly);
    hi = *(uint32_t*)&h; lo = *(uint32_t*)&l;
}

// ===========================================================================
// Tensor-core GEMM: C = A[M,K] @ W[N,K]^T + bias
// mode 0: output bf16 hi/lo row-major (scaled by qscale)
// mode 2: output bf16 hi/lo transposed per-head [b][h][d][s]  (for V)
// mode 3: output fp32
// ===========================================================================
#define GBM 128
#define GBN 128
#define GBK 32
#define GLD (GBK + 8)

__global__ __launch_bounds__(256)
void gemm_nt_bias_tc(const float* __restrict__ A, const float* __restrict__ W,
                     const float* __restrict__ bias, float* __restrict__ Cf,
                     __nv_bfloat16* __restrict__ Oh, __nv_bfloat16* __restrict__ Ol,
                     int M, int N, int K, int mode, float qscale)
{
    __shared__ __nv_bfloat16 Ah[GBM][GLD], Al[GBM][GLD];
    __shared__ __nv_bfloat16 Wh[GBN][GLD], Wl[GBN][GLD];

    const int tid  = threadIdx.x;
    const int lane = tid & 31;
    const int warp = tid >> 5;
    const int wm   = warp & 3;
    const int wn   = warp >> 2;
    const int g    = lane >> 2;
    const int tg   = lane & 3;
    const int bM   = blockIdx.y * GBM;
    const int bN   = blockIdx.x * GBN;

    const int lr = tid >> 1;
    const int lc = (tid & 1) * 16;

    const float* Ap = A + (size_t)(bM + lr) * K + lc;
    const float* Wp = W + (size_t)(bN + lr) * K + lc;

    float acc[2][8][4];
    #pragma unroll
    for (int i = 0; i < 2; i++)
        #pragma unroll
        for (int j = 0; j < 8; j++)
            #pragma unroll
            for (int t = 0; t < 4; t++) acc[i][j][t] = 0.f;

    for (int k0 = 0; k0 < K; k0 += GBK) {
        float4 av[4], wv[4];
        #pragma unroll
        for (int j = 0; j < 4; j++) {
            av[j] = *(const float4*)(Ap + k0 + j * 4);
            wv[j] = *(const float4*)(Wp + k0 + j * 4);
        }
        __syncthreads();
        #pragma unroll
        for (int j = 0; j < 4; j++) {
            const int c = lc + j * 4;
            uint32_t h0, l0, h1, l1;
            split2(av[j].x, av[j].y, h0, l0);
            split2(av[j].z, av[j].w, h1, l1);
            *(uint32_t*)&Ah[lr][c]     = h0;  *(uint32_t*)&Al[lr][c]     = l0;
            *(uint32_t*)&Ah[lr][c + 2] = h1;  *(uint32_t*)&Al[lr][c + 2] = l1;
            split2(wv[j].x, wv[j].y, h0, l0);
            split2(wv[j].z, wv[j].w, h1, l1);
            *(uint32_t*)&Wh[lr][c]     = h0;  *(uint32_t*)&Wl[lr][c]     = l0;
            *(uint32_t*)&Wh[lr][c + 2] = h1;  *(uint32_t*)&Wl[lr][c + 2] = l1;
        }
        __syncthreads();

        #pragma unroll
        for (int ks = 0; ks < GBK; ks += 16) {
            uint32_t ah[2][4], al[2][4], bh[8][2], bl[8][2];
            #pragma unroll
            for (int mt = 0; mt < 2; mt++) {
                const int r0 = wm * 32 + mt * 16;
                ah[mt][0] = *(const uint32_t*)&Ah[r0 + g    ][ks + 2 * tg    ];
                ah[mt][1] = *(const uint32_t*)&Ah[r0 + 8 + g][ks + 2 * tg    ];
                ah[mt][2] = *(const uint32_t*)&Ah[r0 + g    ][ks + 2 * tg + 8];
                ah[mt][3] = *(const uint32_t*)&Ah[r0 + 8 + g][ks + 2 * tg + 8];
                al[mt][0] = *(const uint32_t*)&Al[r0 + g    ][ks + 2 * tg    ];
                al[mt][1] = *(const uint32_t*)&Al[r0 + 8 + g][ks + 2 * tg    ];
                al[mt][2] = *(const uint32_t*)&Al[r0 + g    ][ks + 2 * tg + 8];
                al[mt][3] = *(const uint32_t*)&Al[r0 + 8 + g][ks + 2 * tg + 8];
            }
            #pragma unroll
            for (int nt = 0; nt < 8; nt++) {
                const int c0 = wn * 64 + nt * 8;
                bh[nt][0] = *(const uint32_t*)&Wh[c0 + g][ks + 2 * tg    ];
                bh[nt][1] = *(const uint32_t*)&Wh[c0 + g][ks + 2 * tg + 8];
                bl[nt][0] = *(const uint32_t*)&Wl[c0 + g][ks + 2 * tg    ];
                bl[nt][1] = *(const uint32_t*)&Wl[c0 + g][ks + 2 * tg + 8];
            }
            #pragma unroll
            for (int mt = 0; mt < 2; mt++)
                #pragma unroll
                for (int nt = 0; nt < 8; nt++) {
                    mma16816(acc[mt][nt], ah[mt], bh[nt][0], bh[nt][1]);
                    mma16816(acc[mt][nt], ah[mt], bl[nt][0], bl[nt][1]);
                    mma16816(acc[mt][nt], al[mt], bh[nt][0], bh[nt][1]);
                }
        }
    }

    #pragma unroll
    for (int mt = 0; mt < 2; mt++) {
        #pragma unroll
        for (int nt = 0; nt < 8; nt++) {
            const int col = bN + wn * 64 + nt * 8 + 2 * tg;
            const float b0 = bias[col], b1 = bias[col + 1];
            const int r0 = bM + wm * 32 + mt * 16 + g;
            float v00 = acc[mt][nt][0] + b0, v01 = acc[mt][nt][1] + b1;
            float v10 = acc[mt][nt][2] + b0, v11 = acc[mt][nt][3] + b1;
            if (mode == 3) {
                *(float2*)&Cf[(size_t)r0 * N + col]       = make_float2(v00, v01);
                *(float2*)&Cf[(size_t)(r0 + 8) * N + col] = make_float2(v10, v11);
            } else if (mode == 0) {
                v00 *= qscale; v01 *= qscale; v10 *= qscale; v11 *= qscale;
                uint32_t h, l;
                split2(v00, v01, h, l);
                *(uint32_t*)&Oh[(size_t)r0 * N + col] = h;
                *(uint32_t*)&Ol[(size_t)r0 * N + col] = l;
                split2(v10, v11, h, l);
                *(uint32_t*)&Oh[(size_t)(r0 + 8) * N + col] = h;
                *(uint32_t*)&Ol[(size_t)(r0 + 8) * N + col] = l;
            } else { // mode 2: V transposed per head: [b][h][d][s]
                #pragma unroll
                for (int rr = 0; rr < 2; rr++) {
                    const int r  = r0 + rr * 8;
                    const int bb = r >> 11;
                    const int s  = r & 2047;
                    const float x0 = rr ? v10 : v00;
                    const float x1 = rr ? v11 : v01;
                    #pragma unroll
                    for (int cc = 0; cc < 2; cc++) {
                        const int c  = col + cc;
                        const int hh = c >> 6;
                        const int d  = c & 63;
                        const float x = cc ? x1 : x0;
                        const size_t idx = (((size_t)bb * Hh + hh) * DKh + d) * Sseq + s;
                        __nv_bfloat16 hi = __float2bfloat16(x);
                        __nv_bfloat16 lo = __float2bfloat16(x - __bfloat162float(hi));
                        Oh[idx] = hi;
                        Ol[idx] = lo;
                    }
                }
            }
        }
    }
}

// ===========================================================================
// Tensor-core flash attention.
// Block: 128 threads (4 warps), 64 query rows (warp w -> rows w*16..+15).
// Per kv tile (64 keys): S = Q K^T (3-split MMA), in-register softmax,
// P V via C-frag -> A-frag repack (3-split MMA). V pre-transposed in gmem.
// ===========================================================================
#define ALD 72   // smem row stride (bf16) -> conflict-free b-frag LDS

__global__ __launch_bounds__(128)
void attn_tc()
{
    __shared__ __nv_bfloat16 Ksh[64][ALD], Ksl[64][ALD];
    __shared__ __nv_bfloat16 Vsh[64][ALD], Vsl[64][ALD];

    const int tid  = threadIdx.x;
    const int lane = tid & 31;
    const int warp = tid >> 5;
    const int g    = lane >> 2;
    const int tg   = lane & 3;
    const int b    = blockIdx.z;
    const int h    = blockIdx.y;
    const int q0   = blockIdx.x * 64;

    // ---- Q fragments (rows warp*16 + g/g+8), loaded once from gmem ----
    uint32_t qh[4][4], ql[4][4];
    {
        const __nv_bfloat16* Qh = g_Qh + (size_t)(b * Sseq + q0 + warp * 16) * Dm + h * DKh;
        const __nv_bfloat16* Ql = g_Ql + (size_t)(b * Sseq + q0 + warp * 16) * Dm + h * DKh;
        #pragma unroll
        for (int ks = 0; ks < 4; ks++) {
            const int c0 = ks * 16 + 2 * tg;
            qh[ks][0] = *(const uint32_t*)&Qh[(size_t)g * Dm + c0];
            qh[ks][1] = *(const uint32_t*)&Qh[(size_t)(g + 8) * Dm + c0];
            qh[ks][2] = *(const uint32_t*)&Qh[(size_t)g * Dm + c0 + 8];
            qh[ks][3] = *(const uint32_t*)&Qh[(size_t)(g + 8) * Dm + c0 + 8];
            ql[ks][0] = *(const uint32_t*)&Ql[(size_t)g * Dm + c0];
            ql[ks][1] = *(const uint32_t*)&Ql[(size_t)(g + 8) * Dm + c0];
            ql[ks][2] = *(const uint32_t*)&Ql[(size_t)g * Dm + c0 + 8];
            ql[ks][3] = *(const uint32_t*)&Ql[(size_t)(g + 8) * Dm + c0 + 8];
        }
    }

    float o[8][4];
    #pragma unroll
    for (int nt = 0; nt < 8; nt++)
        #pragma unroll
        for (int t = 0; t < 4; t++) o[nt][t] = 0.f;
    float m0 = -1e30f, m1 = -1e30f, l0 = 0.f, l1 = 0.f;

    const __nv_bfloat16* Kbh = g_Kh + (size_t)b * Sseq * Dm + h * DKh;
    const __nv_bfloat16* Kbl = g_Kl + (size_t)b * Sseq * Dm + h * DKh;
    const __nv_bfloat16* Vbh = g_Vth + ((size_t)b * Hh + h) * DKh * Sseq;
    const __nv_bfloat16* Vbl = g_Vtl + ((size_t)b * Hh + h) * DKh * Sseq;

    for (int kv0 = 0; kv0 < Sseq; kv0 += 64) {
        __syncthreads();
        // K tile: rows = key, 64 bf16 per row; V tile: rows = d, cols = key
        #pragma unroll
        for (int j = 0; j < 4; j++) {
            const int idx = tid + j * 128;
            const int r = idx >> 3, c = (idx & 7) * 8;
            *(float4*)&Ksh[r][c] = *(const float4*)&Kbh[(size_t)(kv0 + r) * Dm + c];
            *(float4*)&Ksl[r][c] = *(const float4*)&Kbl[(size_t)(kv0 + r) * Dm + c];
            *(float4*)&Vsh[r][c] = *(const float4*)&Vbh[(size_t)r * Sseq + kv0 + c];
            *(float4*)&Vsl[r][c] = *(const float4*)&Vbl[(size_t)r * Sseq + kv0 + c];
        }
        __syncthreads();

        // ---- S = Q K^T ----
        float s[8][4];
        #pragma unroll
        for (int nt = 0; nt < 8; nt++)
            #pragma unroll
            for (int t = 0; t < 4; t++) s[nt][t] = 0.f;
        #pragma unroll
        for (int ks = 0; ks < 4; ks++) {
            const int c0 = ks * 16 + 2 * tg;
            #pragma unroll
            for (int nt = 0; nt < 8; nt++) {
                const int r = nt * 8 + g;
                const uint32_t bh0 = *(const uint32_t*)&Ksh[r][c0];
                const uint32_t bh1 = *(const uint32_t*)&Ksh[r][c0 + 8];
                const uint32_t bl0 = *(const uint32_t*)&Ksl[r][c0];
                const uint32_t bl1 = *(const uint32_t*)&Ksl[r][c0 + 8];
                mma16816(s[nt], qh[ks], bh0, bh1);
                mma16816(s[nt], qh[ks], bl0, bl1);
                mma16816(s[nt], ql[ks], bh0, bh1);
            }
        }

        // ---- online softmax (rows g and g+8) ----
        float mx0 = -1e30f, mx1 = -1e30f;
        #pragma unroll
        for (int nt = 0; nt < 8; nt++) {
            mx0 = fmaxf(mx0, fmaxf(s[nt][0], s[nt][1]));
            mx1 = fmaxf(mx1, fmaxf(s[nt][2], s[nt][3]));
        }
        mx0 = fmaxf(mx0, __shfl_xor_sync(0xffffffffu, mx0, 1));
        mx0 = fmaxf(mx0, __shfl_xor_sync(0xffffffffu, mx0, 2));
        mx1 = fmaxf(mx1, __shfl_xor_sync(0xffffffffu, mx1, 1));
        mx1 = fmaxf(mx1, __shfl_xor_sync(0xffffffffu, mx1, 2));
        const float nm0 = fmaxf(m0, mx0), nm1 = fmaxf(m1, mx1);
        const float sc0 = __expf(m0 - nm0), sc1 = __expf(m1 - nm1);
        m0 = nm0; m1 = nm1;
        l0 *= sc0; l1 *= sc1;
        #pragma unroll
        for (int nt = 0; nt < 8; nt++) {
            o[nt][0] *= sc0; o[nt][1] *= sc0;
            o[nt][2] *= sc1; o[nt][3] *= sc1;
        }

        // ---- P = exp(S - m); PV MMA per k-step (C-frag -> A-frag repack) ----
        #pragma unroll
        for (int ks = 0; ks < 4; ks++) {
            const float e00 = __expf(s[2 * ks][0] - nm0);
            const float e01 = __expf(s[2 * ks][1] - nm0);
            const float e10 = __expf(s[2 * ks][2] - nm1);
            const float e11 = __expf(s[2 * ks][3] - nm1);
            const float f00 = __expf(s[2 * ks + 1][0] - nm0);
            const float f01 = __expf(s[2 * ks + 1][1] - nm0);
            const float f10 = __expf(s[2 * ks + 1][2] - nm1);
            const float f11 = __expf(s[2 * ks + 1][3] - nm1);
            l0 += (e00 + e01) + (f00 + f01);
            l1 += (e10 + e11) + (f10 + f11);
            uint32_t ph[4], pl[4];
            split2(e00, e01, ph[0], pl[0]);
            split2(e10, e11, ph[1], pl[1]);
            split2(f00, f01, ph[2], pl[2]);
            split2(f10, f11, ph[3], pl[3]);
            const int c0 = ks * 16 + 2 * tg;
            #pragma unroll
            for (int nt = 0; nt < 8; nt++) {
                const int r = nt * 8 + g;
                const uint32_t bh0 = *(const uint32_t*)&Vsh[r][c0];
                const uint32_t bh1 = *(const uint32_t*)&Vsh[r][c0 + 8];
                const uint32_t bl0 = *(const uint32_t*)&Vsl[r][c0];
                const uint32_t bl1 = *(const uint32_t*)&Vsl[r][c0 + 8];
                mma16816(o[nt], ph, bh0, bh1);
                mma16816(o[nt], ph, bl0, bl1);
                mma16816(o[nt], pl, bh0, bh1);
            }
        }
    }

    // ---- final normalize + store ----
    l0 += __shfl_xor_sync(0xffffffffu, l0, 1);
    l0 += __shfl_xor_sync(0xffffffffu, l0, 2);
    l1 += __shfl_xor_sync(0xffffffffu, l1, 1);
    l1 += __shfl_xor_sync(0xffffffffu, l1, 2);
    const float i0 = 1.f / l0, i1 = 1.f / l1;

    float* Op = g_Ctx + (size_t)(b * Sseq + q0 + warp * 16) * Dm + h * DKh;
    #pragma unroll
    for (int nt = 0; nt < 8; nt++) {
        const int c = nt * 8 + 2 * tg;
        *(float2*)&Op[(size_t)g * Dm + c]       = make_float2(o[nt][0] * i0, o[nt][1] * i0);
        *(float2*)&Op[(size_t)(g + 8) * Dm + c] = make_float2(o[nt][2] * i1, o[nt][3] * i1);
    }
}

// ---------------------------------------------------------------------------
// Launch
// ---------------------------------------------------------------------------
extern "C" void kernel_launch(void* const* d_in, const int* in_sizes, int n_in,
                              void* d_out, int out_size)
{
    const float* q  = (const float*)d_in[0];
    const float* k  = (const float*)d_in[1];
    const float* v  = (const float*)d_in[2];
    const float* wq = (const float*)d_in[3];
    const float* bq = (const float*)d_in[4];
    const float* wk = (const float*)d_in[5];
    const float* bk = (const float*)d_in[6];
    const float* wv = (const float*)d_in[7];
    const float* bv = (const float*)d_in[8];
    const float* wo = (const float*)d_in[9];
    const float* bo = (const float*)d_in[10];
    float* out = (float*)d_out;

    __nv_bfloat16 *Qh, *Ql, *Kh, *Kl, *Vth, *Vtl;
    float* Ctx;
    cudaGetSymbolAddress((void**)&Qh,  g_Qh);
    cudaGetSymbolAddress((void**)&Ql,  g_Ql);
    cudaGetSymbolAddress((void**)&Kh,  g_Kh);
    cudaGetSymbolAddress((void**)&Kl,  g_Kl);
    cudaGetSymbolAddress((void**)&Vth, g_Vth);
    cudaGetSymbolAddress((void**)&Vtl, g_Vtl);
    cudaGetSymbolAddress((void**)&Ctx, g_Ctx);

    const dim3 gg(Dm / GBN, Mrows / GBM);   // (8, 32)
    gemm_nt_bias_tc<<<gg, 256>>>(q, wq, bq, nullptr, Qh, Ql, Mrows, Dm, Dm, 0, 0.125f);
    gemm_nt_bias_tc<<<gg, 256>>>(k, wk, bk, nullptr, Kh, Kl, Mrows, Dm, Dm, 0, 1.0f);
    gemm_nt_bias_tc<<<gg, 256>>>(v, wv, bv, nullptr, Vth, Vtl, Mrows, Dm, Dm, 2, 1.0f);

    const dim3 ga(Sseq / 64, Hh, Bsz);      // (32, 16, 2)
    attn_tc<<<ga, 128>>>();

    gemm_nt_bias_tc<<<gg, 256>>>(Ctx, wo, bo, out, nullptr, nullptr, Mrows, Dm, Dm, 3, 1.0f);
}

// round 4
// speedup vs baseline: 3.0819x; 1.1529x over previous
#include <cuda_runtime.h>
#include <cuda_bf16.h>
#include <cstdint>

// Problem constants
#define Bsz   2
#define Sseq  2048
#define Dm    1024
#define Hh    16
#define DKh   64
#define Mrows (Bsz * Sseq)   // 4096

typedef __nv_bfloat16 bf;

// ---- scratch (__device__ globals; no allocation allowed) ----
// split inputs
__device__ bf g_xqh[Mrows * Dm], g_xql[Mrows * Dm];
__device__ bf g_xkh[Mrows * Dm], g_xkl[Mrows * Dm];
__device__ bf g_xvh[Mrows * Dm], g_xvl[Mrows * Dm];
__device__ bf g_wqh[Dm * Dm], g_wql[Dm * Dm];
__device__ bf g_wkh[Dm * Dm], g_wkl[Dm * Dm];
__device__ bf g_wvh[Dm * Dm], g_wvl[Dm * Dm];
__device__ bf g_woh[Dm * Dm], g_wol[Dm * Dm];
// projections
__device__ bf g_Qh[Mrows * Dm], g_Ql[Mrows * Dm];
__device__ bf g_Kh[Mrows * Dm], g_Kl[Mrows * Dm];
__device__ bf g_Vth[Mrows * Dm], g_Vtl[Mrows * Dm];  // [b][h][d][s]
// attention output
__device__ bf g_Ctxh[Mrows * Dm], g_Ctxl[Mrows * Dm];

// ===========================================================================
// helpers
// ===========================================================================
__device__ __forceinline__ void mma16816(float* c, const uint32_t* a, uint32_t b0, uint32_t b1)
{
    asm volatile(
        "mma.sync.aligned.m16n8k16.row.col.f32.bf16.bf16.f32 "
        "{%0,%1,%2,%3}, {%4,%5,%6,%7}, {%8,%9}, {%0,%1,%2,%3};\n"
        : "+f"(c[0]), "+f"(c[1]), "+f"(c[2]), "+f"(c[3])
        : "r"(a[0]), "r"(a[1]), "r"(a[2]), "r"(a[3]), "r"(b0), "r"(b1));
}

__device__ __forceinline__ void split2(float x, float y, uint32_t& hi, uint32_t& lo)
{
    bf hx = __float2bfloat16(x), hy = __float2bfloat16(y);
    bf lx = __float2bfloat16(x - __bfloat162float(hx));
    bf ly = __float2bfloat16(y - __bfloat162float(hy));
    __nv_bfloat162 h(hx, hy), l(lx, ly);
    hi = *(uint32_t*)&h; lo = *(uint32_t*)&l;
}

__device__ __forceinline__ uint32_t smem_u32(const void* p)
{
    uint32_t a;
    asm("{ .reg .u64 t; cvta.to.shared.u64 t, %1; cvt.u32.u64 %0, t; }" : "=r"(a) : "l"(p));
    return a;
}
__device__ __forceinline__ void cp16(uint32_t dst, const void* src)
{
    asm volatile("cp.async.ca.shared.global [%0], [%1], 16;\n" :: "r"(dst), "l"(src));
}
#define CP_COMMIT() asm volatile("cp.async.commit_group;\n" ::: "memory")
#define CP_WAIT(n)  asm volatile("cp.async.wait_group %0;\n" :: "n"(n) : "memory")

// ===========================================================================
// pre-split: fp32 -> bf16 hi/lo for all inputs (z selects tensor)
// ===========================================================================
__global__ __launch_bounds__(256)
void split_all(const float* q, const float* k, const float* v,
               const float* wq, const float* wk, const float* wv, const float* wo)
{
    const int z = blockIdx.y;
    const float* src; bf *hi, *lo; int n;
    switch (z) {
        case 0: src = q;  hi = g_xqh; lo = g_xql; n = Mrows * Dm; break;
        case 1: src = k;  hi = g_xkh; lo = g_xkl; n = Mrows * Dm; break;
        case 2: src = v;  hi = g_xvh; lo = g_xvl; n = Mrows * Dm; break;
        case 3: src = wq; hi = g_wqh; lo = g_wql; n = Dm * Dm;    break;
        case 4: src = wk; hi = g_wkh; lo = g_wkl; n = Dm * Dm;    break;
        case 5: src = wv; hi = g_wvh; lo = g_wvl; n = Dm * Dm;    break;
        default: src = wo; hi = g_woh; lo = g_wol; n = Dm * Dm;   break;
    }
    const int t = blockIdx.x * 256 + threadIdx.x;
    if (t * 4 >= n) return;
    const float4 x = ((const float4*)src)[t];
    uint32_t h0, l0, h1, l1;
    split2(x.x, x.y, h0, l0);
    split2(x.z, x.w, h1, l1);
    ((uint2*)hi)[t] = make_uint2(h0, h1);
    ((uint2*)lo)[t] = make_uint2(l0, l1);
}

// ===========================================================================
// Tensor-core GEMM on pre-split bf16: C = A[M,K] @ W[N,K]^T + bias
// cp.async 2-stage pipeline, 128x128 tile, BK=32, 256 threads (8 warps).
// mode 0: out bf16 hi/lo row-major (scaled); mode 2: transposed per head; mode 3: fp32
// ===========================================================================
#define GBK 32
#define GST 40                       // smem row stride (bf16 elems), conflict-free
#define ARR_E (128 * GST)            // 5120 elems per array
#define STG_E (4 * ARR_E)            // 20480 elems per stage
#define STG_B (STG_E * 2)            // 40960 bytes
#define SMEM_TOT (2 * STG_B)         // 81920 bytes

__global__ __launch_bounds__(256)
void gemm_bf16(const bf* __restrict__ Ah, const bf* __restrict__ Al,
               const bf* __restrict__ Wh, const bf* __restrict__ Wl,
               const float* __restrict__ bias, float* __restrict__ Cf,
               bf* __restrict__ Oh, bf* __restrict__ Ol,
               int M, int N, int K, int mode, float qscale)
{
    extern __shared__ bf dsm[];
    const uint32_t sbase = smem_u32(dsm);

    const int tid  = threadIdx.x;
    const int lane = tid & 31;
    const int warp = tid >> 5;
    const int wm   = warp & 3;
    const int wn   = warp >> 2;
    const int g    = lane >> 4 ? 0 : 0;  // placeholder (avoid unused warn)
    const int gg8  = lane >> 2;          // 0..7
    const int tg   = lane & 3;           // 0..3
    const int bM   = blockIdx.y * 128;
    const int bN   = blockIdx.x * 128;

    // cp.async mapping: thread -> row (tid>>1), half (tid&1) -> two 16B chunks
    const int lr = tid >> 1;
    const int lq = tid & 1;
    const bf* gA_h = Ah + (size_t)(bM + lr) * K + lq * 16;
    const bf* gA_l = Al + (size_t)(bM + lr) * K + lq * 16;
    const bf* gW_h = Wh + (size_t)(bN + lr) * K + lq * 16;
    const bf* gW_l = Wl + (size_t)(bN + lr) * K + lq * 16;
    const uint32_t drow = lr * (GST * 2) + lq * 32;   // byte offset within array

    float acc[2][8][4];
    #pragma unroll
    for (int i = 0; i < 2; i++)
        #pragma unroll
        for (int j = 0; j < 8; j++)
            #pragma unroll
            for (int t = 0; t < 4; t++) acc[i][j][t] = 0.f;

    const int nch = K / GBK;   // 32

    // prologue: chunk 0 -> stage 0
    {
        const uint32_t d0 = sbase + drow;
        cp16(d0,                         gA_h);
        cp16(d0 + 16,                    gA_h + 8);
        cp16(d0 + ARR_E * 2,             gA_l);
        cp16(d0 + ARR_E * 2 + 16,        gA_l + 8);
        cp16(d0 + ARR_E * 4,             gW_h);
        cp16(d0 + ARR_E * 4 + 16,        gW_h + 8);
        cp16(d0 + ARR_E * 6,             gW_l);
        cp16(d0 + ARR_E * 6 + 16,        gW_l + 8);
        CP_COMMIT();
    }

    for (int i = 0; i < nch; i++) {
        if (i + 1 < nch) {
            const int k0 = (i + 1) * GBK;
            const uint32_t d0 = sbase + ((i + 1) & 1) * STG_B + drow;
            cp16(d0,                  gA_h + k0);
            cp16(d0 + 16,             gA_h + k0 + 8);
            cp16(d0 + ARR_E * 2,      gA_l + k0);
            cp16(d0 + ARR_E * 2 + 16, gA_l + k0 + 8);
            cp16(d0 + ARR_E * 4,      gW_h + k0);
            cp16(d0 + ARR_E * 4 + 16, gW_h + k0 + 8);
            cp16(d0 + ARR_E * 6,      gW_l + k0);
            cp16(d0 + ARR_E * 6 + 16, gW_l + k0 + 8);
            CP_COMMIT();
            CP_WAIT(1);
        } else {
            CP_WAIT(0);
        }
        __syncthreads();

        const bf* sA_h = dsm + (i & 1) * STG_E;
        const bf* sA_l = sA_h + ARR_E;
        const bf* sW_h = sA_h + 2 * ARR_E;
        const bf* sW_l = sA_h + 3 * ARR_E;

        #pragma unroll
        for (int ks = 0; ks < GBK; ks += 16) {
            uint32_t ah[2][4], al[2][4], bh[8][2], bl[8][2];
            #pragma unroll
            for (int mt = 0; mt < 2; mt++) {
                const int r0 = wm * 32 + mt * 16;
                const int c0 = ks + 2 * tg;
                ah[mt][0] = *(const uint32_t*)&sA_h[(r0 + gg8)     * GST + c0];
                ah[mt][1] = *(const uint32_t*)&sA_h[(r0 + 8 + gg8) * GST + c0];
                ah[mt][2] = *(const uint32_t*)&sA_h[(r0 + gg8)     * GST + c0 + 8];
                ah[mt][3] = *(const uint32_t*)&sA_h[(r0 + 8 + gg8) * GST + c0 + 8];
                al[mt][0] = *(const uint32_t*)&sA_l[(r0 + gg8)     * GST + c0];
                al[mt][1] = *(const uint32_t*)&sA_l[(r0 + 8 + gg8) * GST + c0];
                al[mt][2] = *(const uint32_t*)&sA_l[(r0 + gg8)     * GST + c0 + 8];
                al[mt][3] = *(const uint32_t*)&sA_l[(r0 + 8 + gg8) * GST + c0 + 8];
            }
            #pragma unroll
            for (int nt = 0; nt < 8; nt++) {
                const int r = wn * 64 + nt * 8 + gg8;
                const int c0 = ks + 2 * tg;
                bh[nt][0] = *(const uint32_t*)&sW_h[r * GST + c0];
                bh[nt][1] = *(const uint32_t*)&sW_h[r * GST + c0 + 8];
                bl[nt][0] = *(const uint32_t*)&sW_l[r * GST + c0];
                bl[nt][1] = *(const uint32_t*)&sW_l[r * GST + c0 + 8];
            }
            #pragma unroll
            for (int mt = 0; mt < 2; mt++)
                #pragma unroll
                for (int nt = 0; nt < 8; nt++) {
                    mma16816(acc[mt][nt], ah[mt], bh[nt][0], bh[nt][1]);
                    mma16816(acc[mt][nt], ah[mt], bl[nt][0], bl[nt][1]);
                    mma16816(acc[mt][nt], al[mt], bh[nt][0], bh[nt][1]);
                }
        }
        __syncthreads();
    }

    // ---- epilogue ----
    #pragma unroll
    for (int mt = 0; mt < 2; mt++) {
        #pragma unroll
        for (int nt = 0; nt < 8; nt++) {
            const int col = bN + wn * 64 + nt * 8 + 2 * tg;
            const float b0 = bias[col], b1 = bias[col + 1];
            const int r0 = bM + wm * 32 + mt * 16 + gg8;
            float v00 = acc[mt][nt][0] + b0, v01 = acc[mt][nt][1] + b1;
            float v10 = acc[mt][nt][2] + b0, v11 = acc[mt][nt][3] + b1;
            if (mode == 3) {
                *(float2*)&Cf[(size_t)r0 * N + col]       = make_float2(v00, v01);
                *(float2*)&Cf[(size_t)(r0 + 8) * N + col] = make_float2(v10, v11);
            } else if (mode == 0) {
                v00 *= qscale; v01 *= qscale; v10 *= qscale; v11 *= qscale;
                uint32_t h, l;
                split2(v00, v01, h, l);
                *(uint32_t*)&Oh[(size_t)r0 * N + col] = h;
                *(uint32_t*)&Ol[(size_t)r0 * N + col] = l;
                split2(v10, v11, h, l);
                *(uint32_t*)&Oh[(size_t)(r0 + 8) * N + col] = h;
                *(uint32_t*)&Ol[(size_t)(r0 + 8) * N + col] = l;
            } else { // mode 2: transposed per head [b][h][d][s]
                #pragma unroll
                for (int rr = 0; rr < 2; rr++) {
                    const int r  = r0 + rr * 8;
                    const int bb = r >> 11;
                    const int s  = r & 2047;
                    const float x0 = rr ? v10 : v00;
                    const float x1 = rr ? v11 : v01;
                    #pragma unroll
                    for (int cc = 0; cc < 2; cc++) {
                        const int c  = col + cc;
                        const int hh = c >> 6;
                        const int d  = c & 63;
                        const float x = cc ? x1 : x0;
                        const size_t idx = (((size_t)bb * Hh + hh) * DKh + d) * Sseq + s;
                        bf hi = __float2bfloat16(x);
                        bf lo = __float2bfloat16(x - __bfloat162float(hi));
                        Oh[idx] = hi;
                        Ol[idx] = lo;
                    }
                }
            }
        }
    }
}

// ===========================================================================
// Tensor-core flash attention (as R3) — epilogue now writes bf16 hi/lo Ctx.
// ===========================================================================
#define ALD 72

__global__ __launch_bounds__(128)
void attn_tc()
{
    __shared__ bf Ksh[64][ALD], Ksl[64][ALD];
    __shared__ bf Vsh[64][ALD], Vsl[64][ALD];

    const int tid  = threadIdx.x;
    const int lane = tid & 31;
    const int warp = tid >> 5;
    const int g    = lane >> 2;
    const int tg   = lane & 3;
    const int b    = blockIdx.z;
    const int h    = blockIdx.y;
    const int q0   = blockIdx.x * 64;

    uint32_t qh[4][4], ql[4][4];
    {
        const bf* Qh = g_Qh + (size_t)(b * Sseq + q0 + warp * 16) * Dm + h * DKh;
        const bf* Ql = g_Ql + (size_t)(b * Sseq + q0 + warp * 16) * Dm + h * DKh;
        #pragma unroll
        for (int ks = 0; ks < 4; ks++) {
            const int c0 = ks * 16 + 2 * tg;
            qh[ks][0] = *(const uint32_t*)&Qh[(size_t)g * Dm + c0];
            qh[ks][1] = *(const uint32_t*)&Qh[(size_t)(g + 8) * Dm + c0];
            qh[ks][2] = *(const uint32_t*)&Qh[(size_t)g * Dm + c0 + 8];
            qh[ks][3] = *(const uint32_t*)&Qh[(size_t)(g + 8) * Dm + c0 + 8];
            ql[ks][0] = *(const uint32_t*)&Ql[(size_t)g * Dm + c0];
            ql[ks][1] = *(const uint32_t*)&Ql[(size_t)(g + 8) * Dm + c0];
            ql[ks][2] = *(const uint32_t*)&Ql[(size_t)g * Dm + c0 + 8];
            ql[ks][3] = *(const uint32_t*)&Ql[(size_t)(g + 8) * Dm + c0 + 8];
        }
    }

    float o[8][4];
    #pragma unroll
    for (int nt = 0; nt < 8; nt++)
        #pragma unroll
        for (int t = 0; t < 4; t++) o[nt][t] = 0.f;
    float m0 = -1e30f, m1 = -1e30f, l0 = 0.f, l1 = 0.f;

    const bf* Kbh = g_Kh + (size_t)b * Sseq * Dm + h * DKh;
    const bf* Kbl = g_Kl + (size_t)b * Sseq * Dm + h * DKh;
    const bf* Vbh = g_Vth + ((size_t)b * Hh + h) * DKh * Sseq;
    const bf* Vbl = g_Vtl + ((size_t)b * Hh + h) * DKh * Sseq;

    for (int kv0 = 0; kv0 < Sseq; kv0 += 64) {
        __syncthreads();
        #pragma unroll
        for (int j = 0; j < 4; j++) {
            const int idx = tid + j * 128;
            const int r = idx >> 3, c = (idx & 7) * 8;
            *(float4*)&Ksh[r][c] = *(const float4*)&Kbh[(size_t)(kv0 + r) * Dm + c];
            *(float4*)&Ksl[r][c] = *(const float4*)&Kbl[(size_t)(kv0 + r) * Dm + c];
            *(float4*)&Vsh[r][c] = *(const float4*)&Vbh[(size_t)r * Sseq + kv0 + c];
            *(float4*)&Vsl[r][c] = *(const float4*)&Vbl[(size_t)r * Sseq + kv0 + c];
        }
        __syncthreads();

        float s[8][4];
        #pragma unroll
        for (int nt = 0; nt < 8; nt++)
            #pragma unroll
            for (int t = 0; t < 4; t++) s[nt][t] = 0.f;
        #pragma unroll
        for (int ks = 0; ks < 4; ks++) {
            const int c0 = ks * 16 + 2 * tg;
            #pragma unroll
            for (int nt = 0; nt < 8; nt++) {
                const int r = nt * 8 + g;
                const uint32_t bh0 = *(const uint32_t*)&Ksh[r][c0];
                const uint32_t bh1 = *(const uint32_t*)&Ksh[r][c0 + 8];
                const uint32_t bl0 = *(const uint32_t*)&Ksl[r][c0];
                const uint32_t bl1 = *(const uint32_t*)&Ksl[r][c0 + 8];
                mma16816(s[nt], qh[ks], bh0, bh1);
                mma16816(s[nt], qh[ks], bl0, bl1);
                mma16816(s[nt], ql[ks], bh0, bh1);
            }
        }

        float mx0 = -1e30f, mx1 = -1e30f;
        #pragma unroll
        for (int nt = 0; nt < 8; nt++) {
            mx0 = fmaxf(mx0, fmaxf(s[nt][0], s[nt][1]));
            mx1 = fmaxf(mx1, fmaxf(s[nt][2], s[nt][3]));
        }
        mx0 = fmaxf(mx0, __shfl_xor_sync(0xffffffffu, mx0, 1));
        mx0 = fmaxf(mx0, __shfl_xor_sync(0xffffffffu, mx0, 2));
        mx1 = fmaxf(mx1, __shfl_xor_sync(0xffffffffu, mx1, 1));
        mx1 = fmaxf(mx1, __shfl_xor_sync(0xffffffffu, mx1, 2));
        const float nm0 = fmaxf(m0, mx0), nm1 = fmaxf(m1, mx1);
        const float sc0 = __expf(m0 - nm0), sc1 = __expf(m1 - nm1);
        m0 = nm0; m1 = nm1;
        l0 *= sc0; l1 *= sc1;
        #pragma unroll
        for (int nt = 0; nt < 8; nt++) {
            o[nt][0] *= sc0; o[nt][1] *= sc0;
            o[nt][2] *= sc1; o[nt][3] *= sc1;
        }

        #pragma unroll
        for (int ks = 0; ks < 4; ks++) {
            const float e00 = __expf(s[2 * ks][0] - nm0);
            const float e01 = __expf(s[2 * ks][1] - nm0);
            const float e10 = __expf(s[2 * ks][2] - nm1);
            const float e11 = __expf(s[2 * ks][3] - nm1);
            const float f00 = __expf(s[2 * ks + 1][0] - nm0);
            const float f01 = __expf(s[2 * ks + 1][1] - nm0);
            const float f10 = __expf(s[2 * ks + 1][2] - nm1);
            const float f11 = __expf(s[2 * ks + 1][3] - nm1);
            l0 += (e00 + e01) + (f00 + f01);
            l1 += (e10 + e11) + (f10 + f11);
            uint32_t ph[4], pl[4];
            split2(e00, e01, ph[0], pl[0]);
            split2(e10, e11, ph[1], pl[1]);
            split2(f00, f01, ph[2], pl[2]);
            split2(f10, f11, ph[3], pl[3]);
            const int c0 = ks * 16 + 2 * tg;
            #pragma unroll
            for (int nt = 0; nt < 8; nt++) {
                const int r = nt * 8 + g;
                const uint32_t bh0 = *(const uint32_t*)&Vsh[r][c0];
                const uint32_t bh1 = *(const uint32_t*)&Vsh[r][c0 + 8];
                const uint32_t bl0 = *(const uint32_t*)&Vsl[r][c0];
                const uint32_t bl1 = *(const uint32_t*)&Vsl[r][c0 + 8];
                mma16816(o[nt], ph, bh0, bh1);
                mma16816(o[nt], ph, bl0, bl1);
                mma16816(o[nt], pl, bh0, bh1);
            }
        }
    }

    l0 += __shfl_xor_sync(0xffffffffu, l0, 1);
    l0 += __shfl_xor_sync(0xffffffffu, l0, 2);
    l1 += __shfl_xor_sync(0xffffffffu, l1, 1);
    l1 += __shfl_xor_sync(0xffffffffu, l1, 2);
    const float i0 = 1.f / l0, i1 = 1.f / l1;

    bf* OpH = g_Ctxh + (size_t)(b * Sseq + q0 + warp * 16) * Dm + h * DKh;
    bf* OpL = g_Ctxl + (size_t)(b * Sseq + q0 + warp * 16) * Dm + h * DKh;
    #pragma unroll
    for (int nt = 0; nt < 8; nt++) {
        const int c = nt * 8 + 2 * tg;
        uint32_t h0, l0w, h1, l1w;
        split2(o[nt][0] * i0, o[nt][1] * i0, h0, l0w);
        split2(o[nt][2] * i1, o[nt][3] * i1, h1, l1w);
        *(uint32_t*)&OpH[(size_t)g * Dm + c]       = h0;
        *(uint32_t*)&OpL[(size_t)g * Dm + c]       = l0w;
        *(uint32_t*)&OpH[(size_t)(g + 8) * Dm + c] = h1;
        *(uint32_t*)&OpL[(size_t)(g + 8) * Dm + c] = l1w;
    }
}

// ---------------------------------------------------------------------------
// Launch
// ---------------------------------------------------------------------------
extern "C" void kernel_launch(void* const* d_in, const int* in_sizes, int n_in,
                              void* d_out, int out_size)
{
    const float* q  = (const float*)d_in[0];
    const float* k  = (const float*)d_in[1];
    const float* v  = (const float*)d_in[2];
    const float* wq = (const float*)d_in[3];
    const float* bq = (const float*)d_in[4];
    const float* wk = (const float*)d_in[5];
    const float* bk = (const float*)d_in[6];
    const float* wv = (const float*)d_in[7];
    const float* bv = (const float*)d_in[8];
    const float* wo = (const float*)d_in[9];
    const float* bo = (const float*)d_in[10];
    float* out = (float*)d_out;

    bf *xqh, *xql, *xkh, *xkl, *xvh, *xvl;
    bf *wqh, *wql, *wkh, *wkl, *wvh, *wvl, *woh, *wol;
    bf *Qh, *Ql, *Kh, *Kl, *Vth, *Vtl, *Ch, *Cl;
    cudaGetSymbolAddress((void**)&xqh, g_xqh); cudaGetSymbolAddress((void**)&xql, g_xql);
    cudaGetSymbolAddress((void**)&xkh, g_xkh); cudaGetSymbolAddress((void**)&xkl, g_xkl);
    cudaGetSymbolAddress((void**)&xvh, g_xvh); cudaGetSymbolAddress((void**)&xvl, g_xvl);
    cudaGetSymbolAddress((void**)&wqh, g_wqh); cudaGetSymbolAddress((void**)&wql, g_wql);
    cudaGetSymbolAddress((void**)&wkh, g_wkh); cudaGetSymbolAddress((void**)&wkl, g_wkl);
    cudaGetSymbolAddress((void**)&wvh, g_wvh); cudaGetSymbolAddress((void**)&wvl, g_wvl);
    cudaGetSymbolAddress((void**)&woh, g_woh); cudaGetSymbolAddress((void**)&wol, g_wol);
    cudaGetSymbolAddress((void**)&Qh,  g_Qh);  cudaGetSymbolAddress((void**)&Ql,  g_Ql);
    cudaGetSymbolAddress((void**)&Kh,  g_Kh);  cudaGetSymbolAddress((void**)&Kl,  g_Kl);
    cudaGetSymbolAddress((void**)&Vth, g_Vth); cudaGetSymbolAddress((void**)&Vtl, g_Vtl);
    cudaGetSymbolAddress((void**)&Ch,  g_Ctxh); cudaGetSymbolAddress((void**)&Cl, g_Ctxl);

    cudaFuncSetAttribute(gemm_bf16, cudaFuncAttributeMaxDynamicSharedMemorySize, SMEM_TOT);

    // 1) split all fp32 inputs to bf16 hi/lo
    split_all<<<dim3((Mrows * Dm) / (4 * 256), 7), 256>>>(q, k, v, wq, wk, wv, wo);

    // 2) projections
    const dim3 gg(Dm / 128, Mrows / 128);   // (8, 32)
    gemm_bf16<<<gg, 256, SMEM_TOT>>>(xqh, xql, wqh, wql, bq, nullptr, Qh,  Ql,  Mrows, Dm, Dm, 0, 0.125f);
    gemm_bf16<<<gg, 256, SMEM_TOT>>>(xkh, xkl, wkh, wkl, bk, nullptr, Kh,  Kl,  Mrows, Dm, Dm, 0, 1.0f);
    gemm_bf16<<<gg, 256, SMEM_TOT>>>(xvh, xvl, wvh, wvl, bv, nullptr, Vth, Vtl, Mrows, Dm, Dm, 2, 1.0f);

    // 3) attention
    const dim3 ga(Sseq / 64, Hh, Bsz);      // (32, 16, 2)
    attn_tc<<<ga, 128>>>();

    // 4) output projection
    gemm_bf16<<<gg, 256, SMEM_TOT>>>(Ch, Cl, woh, wol, bo, out, nullptr, nullptr, Mrows, Dm, Dm, 3, 1.0f);
}

// round 5
// speedup vs baseline: 3.2280x; 1.0474x over previous
#include <cuda_runtime.h>
#include <cuda_bf16.h>
#include <cstdint>

// Problem constants
#define Bsz   2
#define Sseq  2048
#define Dm    1024
#define Hh    16
#define DKh   64
#define Mrows (Bsz * Sseq)   // 4096

typedef __nv_bfloat16 bf;

// ---- scratch (__device__ globals; no allocation allowed) ----
__device__ bf g_xqh[Mrows * Dm], g_xql[Mrows * Dm];
__device__ bf g_xkh[Mrows * Dm], g_xkl[Mrows * Dm];
__device__ bf g_xvh[Mrows * Dm], g_xvl[Mrows * Dm];
__device__ bf g_wqh[Dm * Dm], g_wql[Dm * Dm];
__device__ bf g_wkh[Dm * Dm], g_wkl[Dm * Dm];
__device__ bf g_wvh[Dm * Dm], g_wvl[Dm * Dm];
__device__ bf g_woh[Dm * Dm], g_wol[Dm * Dm];
__device__ bf g_Qh[Mrows * Dm], g_Ql[Mrows * Dm];
__device__ bf g_Kh[Mrows * Dm], g_Kl[Mrows * Dm];
__device__ bf g_Vth[Mrows * Dm], g_Vtl[Mrows * Dm];  // [b][h][d][s]
__device__ bf g_Ctxh[Mrows * Dm], g_Ctxl[Mrows * Dm];

// ===========================================================================
// helpers
// ===========================================================================
__device__ __forceinline__ void mma16816(float* c, const uint32_t* a, uint32_t b0, uint32_t b1)
{
    asm volatile(
        "mma.sync.aligned.m16n8k16.row.col.f32.bf16.bf16.f32 "
        "{%0,%1,%2,%3}, {%4,%5,%6,%7}, {%8,%9}, {%0,%1,%2,%3};\n"
        : "+f"(c[0]), "+f"(c[1]), "+f"(c[2]), "+f"(c[3])
        : "r"(a[0]), "r"(a[1]), "r"(a[2]), "r"(a[3]), "r"(b0), "r"(b1));
}

__device__ __forceinline__ void split2(float x, float y, uint32_t& hi, uint32_t& lo)
{
    bf hx = __float2bfloat16(x), hy = __float2bfloat16(y);
    bf lx = __float2bfloat16(x - __bfloat162float(hx));
    bf ly = __float2bfloat16(y - __bfloat162float(hy));
    __nv_bfloat162 h(hx, hy), l(lx, ly);
    hi = *(uint32_t*)&h; lo = *(uint32_t*)&l;
}

__device__ __forceinline__ uint32_t smem_u32(const void* p)
{
    uint32_t a;
    asm("{ .reg .u64 t; cvta.to.shared.u64 t, %1; cvt.u32.u64 %0, t; }" : "=r"(a) : "l"(p));
    return a;
}
__device__ __forceinline__ void cp16(uint32_t dst, const void* src)
{
    asm volatile("cp.async.ca.shared.global [%0], [%1], 16;\n" :: "r"(dst), "l"(src));
}
#define CP_COMMIT() asm volatile("cp.async.commit_group;\n" ::: "memory")
#define CP_WAIT(n)  asm volatile("cp.async.wait_group %0;\n" :: "n"(n) : "memory")

// ===========================================================================
// pre-split: fp32 -> bf16 hi/lo for all inputs (z selects tensor)
// ===========================================================================
__global__ __launch_bounds__(256)
void split_all(const float* q, const float* k, const float* v,
               const float* wq, const float* wk, const float* wv, const float* wo)
{
    const int z = blockIdx.y;
    const float* src; bf *hi, *lo; int n;
    switch (z) {
        case 0: src = q;  hi = g_xqh; lo = g_xql; n = Mrows * Dm; break;
        case 1: src = k;  hi = g_xkh; lo = g_xkl; n = Mrows * Dm; break;
        case 2: src = v;  hi = g_xvh; lo = g_xvl; n = Mrows * Dm; break;
        case 3: src = wq; hi = g_wqh; lo = g_wql; n = Dm * Dm;    break;
        case 4: src = wk; hi = g_wkh; lo = g_wkl; n = Dm * Dm;    break;
        case 5: src = wv; hi = g_wvh; lo = g_wvl; n = Dm * Dm;    break;
        default: src = wo; hi = g_woh; lo = g_wol; n = Dm * Dm;   break;
    }
    const int t = blockIdx.x * 256 + threadIdx.x;
    if (t * 4 >= n) return;
    const float4 x = ((const float4*)src)[t];
    uint32_t h0, l0, h1, l1;
    split2(x.x, x.y, h0, l0);
    split2(x.z, x.w, h1, l1);
    ((uint2*)hi)[t] = make_uint2(h0, h1);
    ((uint2*)lo)[t] = make_uint2(l0, l1);
}

// ===========================================================================
// Unified tensor-core GEMM (pre-split bf16): C = A @ W^T + bias
// z = blockIdx.z + zbase:  0=Q-proj  1=K-proj  2=V-proj(transposed out)  3=O-proj(fp32 out)
// cp.async 2-stage pipeline, 128x128 tile, BK=32, 256 threads,
// __launch_bounds__(256,2) -> <=128 regs -> 2 blocks/SM.
// ===========================================================================
#define GBK 32
#define GST 40
#define ARR_E (128 * GST)
#define STG_E (4 * ARR_E)
#define STG_B (STG_E * 2)
#define SMEM_TOT (2 * STG_B)   // 81920 B

__global__ __launch_bounds__(256, 2)
void gemm_all(int zbase,
              const float* __restrict__ bq, const float* __restrict__ bk,
              const float* __restrict__ bv, const float* __restrict__ bo,
              float* __restrict__ out)
{
    extern __shared__ bf dsm[];
    const uint32_t sbase = smem_u32(dsm);

    const int z = blockIdx.z + zbase;
    const bf *Ah, *Al, *Wh, *Wl;
    const float* bias;
    bf *Oh = nullptr, *Ol = nullptr;
    float* Cf = nullptr;
    int mode; float qscale = 1.0f;
    switch (z) {
        case 0:  Ah = g_xqh; Al = g_xql; Wh = g_wqh; Wl = g_wql; bias = bq;
                 Oh = g_Qh; Ol = g_Ql; mode = 0; qscale = 0.125f; break;
        case 1:  Ah = g_xkh; Al = g_xkl; Wh = g_wkh; Wl = g_wkl; bias = bk;
                 Oh = g_Kh; Ol = g_Kl; mode = 0; break;
        case 2:  Ah = g_xvh; Al = g_xvl; Wh = g_wvh; Wl = g_wvl; bias = bv;
                 Oh = g_Vth; Ol = g_Vtl; mode = 2; break;
        default: Ah = g_Ctxh; Al = g_Ctxl; Wh = g_woh; Wl = g_wol; bias = bo;
                 Cf = out; mode = 3; break;
    }

    const int tid  = threadIdx.x;
    const int lane = tid & 31;
    const int warp = tid >> 5;
    const int wm   = warp & 3;
    const int wn   = warp >> 2;
    const int gg8  = lane >> 2;
    const int tg   = lane & 3;
    const int bM   = blockIdx.y * 128;
    const int bN   = blockIdx.x * 128;
    const int K    = Dm, N = Dm;

    const int lr = tid >> 1;
    const int lq = tid & 1;
    const bf* gA_h = Ah + (size_t)(bM + lr) * K + lq * 16;
    const bf* gA_l = Al + (size_t)(bM + lr) * K + lq * 16;
    const bf* gW_h = Wh + (size_t)(bN + lr) * K + lq * 16;
    const bf* gW_l = Wl + (size_t)(bN + lr) * K + lq * 16;
    const uint32_t drow = lr * (GST * 2) + lq * 32;

    float acc[2][8][4];
    #pragma unroll
    for (int i = 0; i < 2; i++)
        #pragma unroll
        for (int j = 0; j < 8; j++)
            #pragma unroll
            for (int t = 0; t < 4; t++) acc[i][j][t] = 0.f;

    const int nch = K / GBK;   // 32

    {
        const uint32_t d0 = sbase + drow;
        cp16(d0,                  gA_h);
        cp16(d0 + 16,             gA_h + 8);
        cp16(d0 + ARR_E * 2,      gA_l);
        cp16(d0 + ARR_E * 2 + 16, gA_l + 8);
        cp16(d0 + ARR_E * 4,      gW_h);
        cp16(d0 + ARR_E * 4 + 16, gW_h + 8);
        cp16(d0 + ARR_E * 6,      gW_l);
        cp16(d0 + ARR_E * 6 + 16, gW_l + 8);
        CP_COMMIT();
    }

    for (int i = 0; i < nch; i++) {
        if (i + 1 < nch) {
            const int k0 = (i + 1) * GBK;
            const uint32_t d0 = sbase + ((i + 1) & 1) * STG_B + drow;
            cp16(d0,                  gA_h + k0);
            cp16(d0 + 16,             gA_h + k0 + 8);
            cp16(d0 + ARR_E * 2,      gA_l + k0);
            cp16(d0 + ARR_E * 2 + 16, gA_l + k0 + 8);
            cp16(d0 + ARR_E * 4,      gW_h + k0);
            cp16(d0 + ARR_E * 4 + 16, gW_h + k0 + 8);
            cp16(d0 + ARR_E * 6,      gW_l + k0);
            cp16(d0 + ARR_E * 6 + 16, gW_l + k0 + 8);
            CP_COMMIT();
            CP_WAIT(1);
        } else {
            CP_WAIT(0);
        }
        __syncthreads();

        const bf* sA_h = dsm + (i & 1) * STG_E;
        const bf* sA_l = sA_h + ARR_E;
        const bf* sW_h = sA_h + 2 * ARR_E;
        const bf* sW_l = sA_h + 3 * ARR_E;

        #pragma unroll
        for (int ks = 0; ks < GBK; ks += 16) {
            uint32_t ah[2][4], al[2][4], bh[8][2], bl[8][2];
            #pragma unroll
            for (int mt = 0; mt < 2; mt++) {
                const int r0 = wm * 32 + mt * 16;
                const int c0 = ks + 2 * tg;
                ah[mt][0] = *(const uint32_t*)&sA_h[(r0 + gg8)     * GST + c0];
                ah[mt][1] = *(const uint32_t*)&sA_h[(r0 + 8 + gg8) * GST + c0];
                ah[mt][2] = *(const uint32_t*)&sA_h[(r0 + gg8)     * GST + c0 + 8];
                ah[mt][3] = *(const uint32_t*)&sA_h[(r0 + 8 + gg8) * GST + c0 + 8];
                al[mt][0] = *(const uint32_t*)&sA_l[(r0 + gg8)     * GST + c0];
                al[mt][1] = *(const uint32_t*)&sA_l[(r0 + 8 + gg8) * GST + c0];
                al[mt][2] = *(const uint32_t*)&sA_l[(r0 + gg8)     * GST + c0 + 8];
                al[mt][3] = *(const uint32_t*)&sA_l[(r0 + 8 + gg8) * GST + c0 + 8];
            }
            #pragma unroll
            for (int nt = 0; nt < 8; nt++) {
                const int r = wn * 64 + nt * 8 + gg8;
                const int c0 = ks + 2 * tg;
                bh[nt][0] = *(const uint32_t*)&sW_h[r * GST + c0];
                bh[nt][1] = *(const uint32_t*)&sW_h[r * GST + c0 + 8];
                bl[nt][0] = *(const uint32_t*)&sW_l[r * GST + c0];
                bl[nt][1] = *(const uint32_t*)&sW_l[r * GST + c0 + 8];
            }
            #pragma unroll
            for (int mt = 0; mt < 2; mt++)
                #pragma unroll
                for (int nt = 0; nt < 8; nt++) {
                    mma16816(acc[mt][nt], ah[mt], bh[nt][0], bh[nt][1]);
                    mma16816(acc[mt][nt], ah[mt], bl[nt][0], bl[nt][1]);
                    mma16816(acc[mt][nt], al[mt], bh[nt][0], bh[nt][1]);
                }
        }
        __syncthreads();
    }

    // ---- epilogue ----
    #pragma unroll
    for (int mt = 0; mt < 2; mt++) {
        #pragma unroll
        for (int nt = 0; nt < 8; nt++) {
            const int col = bN + wn * 64 + nt * 8 + 2 * tg;
            const float b0 = bias[col], b1 = bias[col + 1];
            const int r0 = bM + wm * 32 + mt * 16 + gg8;
            float v00 = acc[mt][nt][0] + b0, v01 = acc[mt][nt][1] + b1;
            float v10 = acc[mt][nt][2] + b0, v11 = acc[mt][nt][3] + b1;
            if (mode == 3) {
                *(float2*)&Cf[(size_t)r0 * N + col]       = make_float2(v00, v01);
                *(float2*)&Cf[(size_t)(r0 + 8) * N + col] = make_float2(v10, v11);
            } else if (mode == 0) {
                v00 *= qscale; v01 *= qscale; v10 *= qscale; v11 *= qscale;
                uint32_t h, l;
                split2(v00, v01, h, l);
                *(uint32_t*)&Oh[(size_t)r0 * N + col] = h;
                *(uint32_t*)&Ol[(size_t)r0 * N + col] = l;
                split2(v10, v11, h, l);
                *(uint32_t*)&Oh[(size_t)(r0 + 8) * N + col] = h;
                *(uint32_t*)&Ol[(size_t)(r0 + 8) * N + col] = l;
            } else { // mode 2: transposed per head [b][h][d][s]
                #pragma unroll
                for (int rr = 0; rr < 2; rr++) {
                    const int r  = r0 + rr * 8;
                    const int bb = r >> 11;
                    const int s  = r & 2047;
                    const float x0 = rr ? v10 : v00;
                    const float x1 = rr ? v11 : v01;
                    #pragma unroll
                    for (int cc = 0; cc < 2; cc++) {
                        const int c  = col + cc;
                        const int hh = c >> 6;
                        const int d  = c & 63;
                        const float x = cc ? x1 : x0;
                        const size_t idx = (((size_t)bb * Hh + hh) * DKh + d) * Sseq + s;
                        bf hi = __float2bfloat16(x);
                        bf lo = __float2bfloat16(x - __bfloat162float(hi));
                        Oh[idx] = hi;
                        Ol[idx] = lo;
                    }
                }
            }
        }
    }
}

// ===========================================================================
// Tensor-core flash attention (verified R3/R4).
// ===========================================================================
#define ALD 72

__global__ __launch_bounds__(128)
void attn_tc()
{
    __shared__ bf Ksh[64][ALD], Ksl[64][ALD];
    __shared__ bf Vsh[64][ALD], Vsl[64][ALD];

    const int tid  = threadIdx.x;
    const int lane = tid & 31;
    const int warp = tid >> 5;
    const int g    = lane >> 2;
    const int tg   = lane & 3;
    const int b    = blockIdx.z;
    const int h    = blockIdx.y;
    const int q0   = blockIdx.x * 64;

    uint32_t qh[4][4], ql[4][4];
    {
        const bf* Qh = g_Qh + (size_t)(b * Sseq + q0 + warp * 16) * Dm + h * DKh;
        const bf* Ql = g_Ql + (size_t)(b * Sseq + q0 + warp * 16) * Dm + h * DKh;
        #pragma unroll
        for (int ks = 0; ks < 4; ks++) {
            const int c0 = ks * 16 + 2 * tg;
            qh[ks][0] = *(const uint32_t*)&Qh[(size_t)g * Dm + c0];
            qh[ks][1] = *(const uint32_t*)&Qh[(size_t)(g + 8) * Dm + c0];
            qh[ks][2] = *(const uint32_t*)&Qh[(size_t)g * Dm + c0 + 8];
            qh[ks][3] = *(const uint32_t*)&Qh[(size_t)(g + 8) * Dm + c0 + 8];
            ql[ks][0] = *(const uint32_t*)&Ql[(size_t)g * Dm + c0];
            ql[ks][1] = *(const uint32_t*)&Ql[(size_t)(g + 8) * Dm + c0];
            ql[ks][2] = *(const uint32_t*)&Ql[(size_t)g * Dm + c0 + 8];
            ql[ks][3] = *(const uint32_t*)&Ql[(size_t)(g + 8) * Dm + c0 + 8];
        }
    }

    float o[8][4];
    #pragma unroll
    for (int nt = 0; nt < 8; nt++)
        #pragma unroll
        for (int t = 0; t < 4; t++) o[nt][t] = 0.f;
    float m0 = -1e30f, m1 = -1e30f, l0 = 0.f, l1 = 0.f;

    const bf* Kbh = g_Kh + (size_t)b * Sseq * Dm + h * DKh;
    const bf* Kbl = g_Kl + (size_t)b * Sseq * Dm + h * DKh;
    const bf* Vbh = g_Vth + ((size_t)b * Hh + h) * DKh * Sseq;
    const bf* Vbl = g_Vtl + ((size_t)b * Hh + h) * DKh * Sseq;

    for (int kv0 = 0; kv0 < Sseq; kv0 += 64) {
        __syncthreads();
        #pragma unroll
        for (int j = 0; j < 4; j++) {
            const int idx = tid + j * 128;
            const int r = idx >> 3, c = (idx & 7) * 8;
            *(float4*)&Ksh[r][c] = *(const float4*)&Kbh[(size_t)(kv0 + r) * Dm + c];
            *(float4*)&Ksl[r][c] = *(const float4*)&Kbl[(size_t)(kv0 + r) * Dm + c];
            *(float4*)&Vsh[r][c] = *(const float4*)&Vbh[(size_t)r * Sseq + kv0 + c];
            *(float4*)&Vsl[r][c] = *(const float4*)&Vbl[(size_t)r * Sseq + kv0 + c];
        }
        __syncthreads();

        float s[8][4];
        #pragma unroll
        for (int nt = 0; nt < 8; nt++)
            #pragma unroll
            for (int t = 0; t < 4; t++) s[nt][t] = 0.f;
        #pragma unroll
        for (int ks = 0; ks < 4; ks++) {
            const int c0 = ks * 16 + 2 * tg;
            #pragma unroll
            for (int nt = 0; nt < 8; nt++) {
                const int r = nt * 8 + g;
                const uint32_t bh0 = *(const uint32_t*)&Ksh[r][c0];
                const uint32_t bh1 = *(const uint32_t*)&Ksh[r][c0 + 8];
                const uint32_t bl0 = *(const uint32_t*)&Ksl[r][c0];
                const uint32_t bl1 = *(const uint32_t*)&Ksl[r][c0 + 8];
                mma16816(s[nt], qh[ks], bh0, bh1);
                mma16816(s[nt], qh[ks], bl0, bl1);
                mma16816(s[nt], ql[ks], bh0, bh1);
            }
        }

        float mx0 = -1e30f, mx1 = -1e30f;
        #pragma unroll
        for (int nt = 0; nt < 8; nt++) {
            mx0 = fmaxf(mx0, fmaxf(s[nt][0], s[nt][1]));
            mx1 = fmaxf(mx1, fmaxf(s[nt][2], s[nt][3]));
        }
        mx0 = fmaxf(mx0, __shfl_xor_sync(0xffffffffu, mx0, 1));
        mx0 = fmaxf(mx0, __shfl_xor_sync(0xffffffffu, mx0, 2));
        mx1 = fmaxf(mx1, __shfl_xor_sync(0xffffffffu, mx1, 1));
        mx1 = fmaxf(mx1, __shfl_xor_sync(0xffffffffu, mx1, 2));
        const float nm0 = fmaxf(m0, mx0), nm1 = fmaxf(m1, mx1);
        const float sc0 = __expf(m0 - nm0), sc1 = __expf(m1 - nm1);
        m0 = nm0; m1 = nm1;
        l0 *= sc0; l1 *= sc1;
        #pragma unroll
        for (int nt = 0; nt < 8; nt++) {
            o[nt][0] *= sc0; o[nt][1] *= sc0;
            o[nt][2] *= sc1; o[nt][3] *= sc1;
        }

        #pragma unroll
        for (int ks = 0; ks < 4; ks++) {
            const float e00 = __expf(s[2 * ks][0] - nm0);
            const float e01 = __expf(s[2 * ks][1] - nm0);
            const float e10 = __expf(s[2 * ks][2] - nm1);
            const float e11 = __expf(s[2 * ks][3] - nm1);
            const float f00 = __expf(s[2 * ks + 1][0] - nm0);
            const float f01 = __expf(s[2 * ks + 1][1] - nm0);
            const float f10 = __expf(s[2 * ks + 1][2] - nm1);
            const float f11 = __expf(s[2 * ks + 1][3] - nm1);
            l0 += (e00 + e01) + (f00 + f01);
            l1 += (e10 + e11) + (f10 + f11);
            uint32_t ph[4], pl[4];
            split2(e00, e01, ph[0], pl[0]);
            split2(e10, e11, ph[1], pl[1]);
            split2(f00, f01, ph[2], pl[2]);
            split2(f10, f11, ph[3], pl[3]);
            const int c0 = ks * 16 + 2 * tg;
            #pragma unroll
            for (int nt = 0; nt < 8; nt++) {
                const int r = nt * 8 + g;
                const uint32_t bh0 = *(const uint32_t*)&Vsh[r][c0];
                const uint32_t bh1 = *(const uint32_t*)&Vsh[r][c0 + 8];
                const uint32_t bl0 = *(const uint32_t*)&Vsl[r][c0];
                const uint32_t bl1 = *(const uint32_t*)&Vsl[r][c0 + 8];
                mma16816(o[nt], ph, bh0, bh1);
                mma16816(o[nt], ph, bl0, bl1);
                mma16816(o[nt], pl, bh0, bh1);
            }
        }
    }

    l0 += __shfl_xor_sync(0xffffffffu, l0, 1);
    l0 += __shfl_xor_sync(0xffffffffu, l0, 2);
    l1 += __shfl_xor_sync(0xffffffffu, l1, 1);
    l1 += __shfl_xor_sync(0xffffffffu, l1, 2);
    const float i0 = 1.f / l0, i1 = 1.f / l1;

    bf* OpH = g_Ctxh + (size_t)(b * Sseq + q0 + warp * 16) * Dm + h * DKh;
    bf* OpL = g_Ctxl + (size_t)(b * Sseq + q0 + warp * 16) * Dm + h * DKh;
    #pragma unroll
    for (int nt = 0; nt < 8; nt++) {
        const int c = nt * 8 + 2 * tg;
        uint32_t h0, l0w, h1, l1w;
        split2(o[nt][0] * i0, o[nt][1] * i0, h0, l0w);
        split2(o[nt][2] * i1, o[nt][3] * i1, h1, l1w);
        *(uint32_t*)&OpH[(size_t)g * Dm + c]       = h0;
        *(uint32_t*)&OpL[(size_t)g * Dm + c]       = l0w;
        *(uint32_t*)&OpH[(size_t)(g + 8) * Dm + c] = h1;
        *(uint32_t*)&OpL[(size_t)(g + 8) * Dm + c] = l1w;
    }
}

// ---------------------------------------------------------------------------
// Launch
// ---------------------------------------------------------------------------
extern "C" void kernel_launch(void* const* d_in, const int* in_sizes, int n_in,
                              void* d_out, int out_size)
{
    const float* q  = (const float*)d_in[0];
    const float* k  = (const float*)d_in[1];
    const float* v  = (const float*)d_in[2];
    const float* wq = (const float*)d_in[3];
    const float* bq = (const float*)d_in[4];
    const float* wk = (const float*)d_in[5];
    const float* bk = (const float*)d_in[6];
    const float* wv = (const float*)d_in[7];
    const float* bv = (const float*)d_in[8];
    const float* wo = (const float*)d_in[9];
    const float* bo = (const float*)d_in[10];
    float* out = (float*)d_out;

    cudaFuncSetAttribute(gemm_all, cudaFuncAttributeMaxDynamicSharedMemorySize, SMEM_TOT);

    // 1) split all fp32 inputs to bf16 hi/lo
    split_all<<<dim3((Mrows * Dm) / (4 * 256), 7), 256>>>(q, k, v, wq, wk, wv, wo);

    // 2) Q, K, V projections — one launch, z = 0..2
    gemm_all<<<dim3(Dm / 128, Mrows / 128, 3), 256, SMEM_TOT>>>(0, bq, bk, bv, bo, out);

    // 3) attention
    attn_tc<<<dim3(Sseq / 64, Hh, Bsz), 128>>>();

    // 4) output projection (z = 3)
    gemm_all<<<dim3(Dm / 128, Mrows / 128, 1), 256, SMEM_TOT>>>(3, bq, bk, bv, bo, out);
}